// round 12
// baseline (speedup 1.0000x reference)
#include <cuda_runtime.h>
#include <cstdint>
#include <math.h>

#define T_LEN 2048
#define D_IN  100
#define HIDN  100
#define G3    300
#define GI_STRIDE 400     // interleaved gi layout: [t][unit][4] = {r,z,n,pad}
#define NTAG  31
#define NC    128         // number of viterbi chunks
#define CH    16          // steps per chunk (NC*CH == T_LEN)
#define NEGINF -1e30f

// Scratch (no allocations allowed -> __device__ globals)
__device__ float g_gi[2][T_LEN * GI_STRIDE]; // input preactivations, interleaved
__device__ float g_H[2][T_LEN * HIDN];    // hidden states (original time index)
__device__ float g_feats[T_LEN * NTAG];   // emission features for batch `seq`
__device__ float g_M[NC * NTAG * 32];     // chunk max-plus matrices, padded stride 32
__device__ float g_E[NC][32];             // chunk entry fv vectors
__device__ __align__(16) unsigned char g_pathLUT[NC * NTAG * CH]; // per-chunk path LUT
__device__ __align__(16) unsigned char g_prevexit[NC * NTAG];     // chunk exit chaining
__device__ float g_score[1];
__device__ int   g_final[1];

__device__ __forceinline__ float tanh_fast(float x) {
    float y;
    asm("tanh.approx.f32 %0, %1;" : "=f"(y) : "f"(x));
    return y;
}
// sigmoid(x) = 0.5*tanh(0.5x) + 0.5  (one MUFU instead of ex2+rcp)
__device__ __forceinline__ float sigmoid_fast(float x) {
    return fmaf(0.5f, tanh_fast(0.5f * x), 0.5f);
}

// ---------------------------------------------------------------------------
// Kernel 1: gi[t][g%100][g/100] = x[t,seq,:] . w_ih[g,:] + b_ih[g]
//           (+ b_hh[g] folded for the r,z gates)
// ---------------------------------------------------------------------------
#define TCHUNK 8
__global__ void gi_kernel(const float* __restrict__ x,
                          const float* __restrict__ w_ih_f, const float* __restrict__ b_ih_f,
                          const float* __restrict__ b_hh_f,
                          const float* __restrict__ w_ih_b, const float* __restrict__ b_ih_b,
                          const float* __restrict__ b_hh_b,
                          const int* __restrict__ seq_p, int B)
{
    const int dir = blockIdx.y;
    const float* w   = dir ? w_ih_b : w_ih_f;
    const float* b   = dir ? b_ih_b : b_ih_f;
    const float* bhh = dir ? b_hh_b : b_hh_f;
    float* out = g_gi[dir];
    const int t0 = blockIdx.x * TCHUNK;
    const int seq = *seq_p;

    __shared__ __align__(16) float xs[TCHUNK * D_IN];
    for (int idx = threadIdx.x; idx < TCHUNK * D_IN; idx += blockDim.x) {
        int tt = idx / D_IN, d = idx - tt * D_IN;
        xs[tt * D_IN + d] = x[(size_t)(t0 + tt) * B * D_IN + (size_t)seq * D_IN + d];
    }
    __syncthreads();

    const int g = threadIdx.x;
    if (g >= G3) return;

    float acc[TCHUNK];
#pragma unroll
    for (int tt = 0; tt < TCHUNK; tt++) acc[tt] = 0.f;

    const float4* wr = (const float4*)(w + g * D_IN);
#pragma unroll
    for (int i = 0; i < D_IN / 4; i++) {
        float4 w4 = wr[i];
#pragma unroll
        for (int tt = 0; tt < TCHUNK; tt++) {
            const float* xp = xs + tt * D_IN + i * 4;
            acc[tt] = fmaf(w4.x, xp[0], acc[tt]);
            acc[tt] = fmaf(w4.y, xp[1], acc[tt]);
            acc[tt] = fmaf(w4.z, xp[2], acc[tt]);
            acc[tt] = fmaf(w4.w, xp[3], acc[tt]);
        }
    }
    // fold b_hh for the r,z gates only (n gate's b_hh is multiplied by r in the cell)
    const float bb = b[g] + ((g < 2 * HIDN) ? bhh[g] : 0.f);
    const int slot = (g % HIDN) * 4 + (g / HIDN);   // interleaved {r,z,n,pad}
#pragma unroll
    for (int tt = 0; tt < TCHUNK; tt++)
        out[(size_t)(t0 + tt) * GI_STRIDE + slot] = acc[tt] + bb;
}

// ---------------------------------------------------------------------------
// Kernel 2: GRU recurrence, one CTA per direction (R8 base). 600 threads,
// thread (j=tid>>1, p=tid&1) computes half of gate-row j's dot with h
// (13 x LDS.128 + 52 FFMA, partials to gh_s).
// CHANGE vs R8: gate duty for unit u sits on thread 2u (the thread that just
// computed r-row u half0). Its full r-sum arrives via one intra-warp
// shfl_down(1) BEFORE the barrier, so r's sigmoid overlaps the BAR1 wait and
// the post-barrier chain is only the z/n legs (2 x LDS.64 shorter).
// ---------------------------------------------------------------------------
__global__ void __launch_bounds__(600, 1) gru_kernel(
    const float* __restrict__ w_hh_f, const float* __restrict__ b_hh_f,
    const float* __restrict__ w_hh_b, const float* __restrict__ b_hh_b)
{
    const int dir = blockIdx.x;
    const float* w_hh = dir ? w_hh_b : w_hh_f;
    const float* b_hh = dir ? b_hh_b : b_hh_f;
    const float* gi   = g_gi[dir];
    float* Hout       = g_H[dir];

    const int tid = threadIdx.x;
    const int j = tid >> 1;
    const int p = tid & 1;
    const bool gate = (tid < 200) && (p == 0);   // thread 2u owns unit u
    const int u = j;                             // unit index for gate threads

    __shared__ __align__(16) float h_s[104];        // padded; [100..103] stay 0
    __shared__ __align__(8)  float gh_s[600];       // partials: row r at [2r],[2r+1]

    // Register-resident weights: columns [52p, 52p+52) of row j (zero pad)
    float wreg[52];
#pragma unroll
    for (int i = 0; i < 52; i++) {
        int col = 52 * p + i;
        wreg[i] = (col < HIDN) ? w_hh[j * HIDN + col] : 0.f;
    }
    float bhh2 = 0.f, h_reg = 0.f;
    if (gate) bhh2 = b_hh[2 * HIDN + u];        // n-gate hidden bias (scaled by r)
    if (tid < 104) h_s[tid] = 0.f;
    const unsigned smask = (tid < 576) ? 0xFFFFFFFFu : 0x00FFFFFFu;  // warp 18: 24 lanes
    __syncthreads();

    // gi prefetch double buffer (gate threads only)
    float4 giv = make_float4(0.f, 0.f, 0.f, 0.f);
    if (gate) {
        const int t0 = dir ? (T_LEN - 1) : 0;
        giv = ((const float4*)(gi + (size_t)t0 * GI_STRIDE))[u];
    }

    for (int step = 0; step < T_LEN; ++step) {
        const int t = dir ? (T_LEN - 1 - step) : step;

        // Prefetch NEXT step's gi (a full step of slack before consumption)
        float4 ginext = make_float4(0.f, 0.f, 0.f, 0.f);
        if (gate && step + 1 < T_LEN) {
            const int tn = dir ? (T_LEN - 2 - step) : (step + 1);
            ginext = ((const float4*)(gi + (size_t)tn * GI_STRIDE))[u];
        }

        // Matvec half-row: 13 x (LDS.128 broadcast + 4 FFMA)
        float a0 = 0.f, a1 = 0.f, a2 = 0.f, a3 = 0.f;
        const float4* hv = (const float4*)(h_s + 52 * p);
#pragma unroll
        for (int i = 0; i < 13; i++) {
            float4 h4 = hv[i];
            a0 = fmaf(wreg[4 * i + 0], h4.x, a0);
            a1 = fmaf(wreg[4 * i + 1], h4.y, a1);
            a2 = fmaf(wreg[4 * i + 2], h4.z, a2);
            a3 = fmaf(wreg[4 * i + 3], h4.w, a3);
        }
        const float partial = (a0 + a1) + (a2 + a3);
        gh_s[2 * j + p] = partial;      // z/n rows consumed after BAR; r rows unused

        // r-gate precompute: full r-sum via one intra-warp shfl, sigmoid
        // overlaps the barrier wait. Same addition order as R8 (half0+half1).
        const float rother = __shfl_down_sync(smask, partial, 1);
        float r = 0.f;
        if (gate) r = sigmoid_fast(giv.x + (partial + rother));

        __syncthreads();

        if (gate) {
            const float2* g2 = (const float2*)gh_s;
            float2 pz = g2[HIDN + u];           // row 100+u   (z gate)
            float2 pn = g2[2 * HIDN + u];       // row 200+u   (n gate)
            float z = sigmoid_fast(giv.y + pz.x + pz.y);
            float hn = (pn.x + pn.y) + bhh2;
            float n = tanh_fast(fmaf(r, hn, giv.z));
            float hnew = fmaf(z, h_reg - n, n);
            h_reg = hnew;
            h_s[u] = hnew;
            Hout[(size_t)t * HIDN + u] = hnew;
        }
        giv = ginext;
        __syncthreads();
    }
}

// ---------------------------------------------------------------------------
// Kernel 3: feats[t][k] = w_out[k,:] . [h_f[t]; h_b[t]] + b_out[k]
// ---------------------------------------------------------------------------
__global__ void feats_kernel(const float* __restrict__ w_out, const float* __restrict__ b_out)
{
    const int t = blockIdx.x;
    __shared__ __align__(16) float hc[2 * HIDN];
    const int tid = threadIdx.x;
    if (tid < HIDN)          hc[tid] = g_H[0][(size_t)t * HIDN + tid];
    else if (tid < 2 * HIDN) hc[tid] = g_H[1][(size_t)t * HIDN + (tid - HIDN)];
    __syncthreads();

    if (tid < NTAG) {
        const float4* wr = (const float4*)(w_out + tid * 2 * HIDN);
        const float4* hv = (const float4*)hc;
        float a0 = 0.f, a1 = 0.f, a2 = 0.f, a3 = 0.f;
#pragma unroll
        for (int i = 0; i < (2 * HIDN) / 4; i++) {
            float4 w4 = wr[i]; float4 h4 = hv[i];
            a0 = fmaf(w4.x, h4.x, a0); a1 = fmaf(w4.y, h4.y, a1);
            a2 = fmaf(w4.z, h4.z, a2); a3 = fmaf(w4.w, h4.w, a3);
        }
        g_feats[t * NTAG + tid] = (a0 + a1) + (a2 + a3) + b_out[tid];
    }
}

// ---------------------------------------------------------------------------
// Viterbi Phase A: per-chunk max-plus matrix product, NC CTAs in parallel.
// ---------------------------------------------------------------------------
__global__ void __launch_bounds__(992, 1) vitA_kernel(
    const float* __restrict__ trans, const float* __restrict__ maskg,
    const int* __restrict__ seq_p)
{
    const int c = blockIdx.x;
    const int tid = threadIdx.x;
    const int w = tid >> 5;
    const int lane = tid & 31;
    const int seq = *seq_p;

    __shared__ float Mbuf[2][NTAG][32];
    __shared__ float featS[CH][32];
    __shared__ float maskS[CH];

    if (tid < CH * NTAG) {
        int lt = tid / NTAG, k = tid - lt * NTAG;
        featS[lt][k] = g_feats[(c * CH + lt) * NTAG + k];
    }
    if (tid < CH) maskS[tid] = maskg[(size_t)seq * T_LEN + c * CH + tid];

    for (int idx = tid; idx < 2 * NTAG * 32; idx += 992) {
        int buf = idx / (NTAG * 32);
        int rem = idx - buf * NTAG * 32;
        int r = rem >> 5, col = rem & 31;
        Mbuf[buf][r][col] = (r == col) ? 0.f : NEGINF;
    }

    float tr[NTAG];
#pragma unroll
    for (int jj = 0; jj < NTAG; jj++) tr[jj] = trans[w * NTAG + jj];
    __syncthreads();

    int src = 0;
    for (int lt = 0; lt < CH; lt++) {
        if (maskS[lt] > 0.f) {
            float f = featS[lt][w];
            float m = NEGINF;
#pragma unroll
            for (int jj = 0; jj < NTAG; jj++)
                m = fmaxf(m, tr[jj] + Mbuf[src][jj][lane]);
            Mbuf[1 - src][w][lane] = m + f;
            __syncthreads();
            src ^= 1;
        }
    }
    g_M[c * NTAG * 32 + w * 32 + lane] = Mbuf[src][w][lane];
}

// ---------------------------------------------------------------------------
// Viterbi Phase B: sequential chunk combine (single warp) with prefetch.
// ---------------------------------------------------------------------------
__global__ void __launch_bounds__(32, 1) vitB_kernel()
{
    const int lane = threadIdx.x;
    const int rowi = (lane < NTAG) ? lane : NTAG - 1;
    float fv = (lane == 0) ? 0.f : ((lane < NTAG) ? -10000.f : NEGINF);

    float cur[32], pre[32];
    {
        const float4* r4 = (const float4*)(g_M + 0 * NTAG * 32 + rowi * 32);
#pragma unroll
        for (int i = 0; i < 8; i++) {
            float4 v = r4[i];
            cur[4 * i] = v.x; cur[4 * i + 1] = v.y; cur[4 * i + 2] = v.z; cur[4 * i + 3] = v.w;
        }
    }

    for (int c = 0; c < NC; c++) {
        if (c + 1 < NC) {
            const float4* r4 = (const float4*)(g_M + (c + 1) * NTAG * 32 + rowi * 32);
#pragma unroll
            for (int i = 0; i < 8; i++) {
                float4 v = r4[i];
                pre[4 * i] = v.x; pre[4 * i + 1] = v.y; pre[4 * i + 2] = v.z; pre[4 * i + 3] = v.w;
            }
        }
        g_E[c][lane] = fv;
        float m = NEGINF;
#pragma unroll
        for (int pp = 0; pp < NTAG; pp++)
            m = fmaxf(m, cur[pp] + __shfl_sync(0xFFFFFFFFu, fv, pp));
        fv = (lane < NTAG) ? m : NEGINF;
#pragma unroll
        for (int i = 0; i < 32; i++) cur[i] = pre[i];
    }
}

// ---------------------------------------------------------------------------
// Viterbi Phase C: per-chunk forward re-run + backpointers + backtrack LUT.
// ---------------------------------------------------------------------------
__global__ void __launch_bounds__(992, 1) vitC_kernel(
    const float* __restrict__ trans, const float* __restrict__ maskg,
    const int* __restrict__ seq_p)
{
    const int c = blockIdx.x;
    const int tid = threadIdx.x;
    const int w = tid >> 5;
    const int lane = tid & 31;
    const int seq = *seq_p;

    __shared__ float fv_s[32];
    __shared__ float transS[NTAG][32];
    __shared__ float featS[CH][32];
    __shared__ float maskS[CH];
    __shared__ unsigned char bp_s[CH][NTAG];

    if (tid < CH * NTAG) {
        int lt = tid / NTAG, k = tid - lt * NTAG;
        featS[lt][k] = g_feats[(c * CH + lt) * NTAG + k];
    }
    if (tid < CH) maskS[tid] = maskg[(size_t)seq * T_LEN + c * CH + tid];
    if (lane < NTAG) transS[w][lane] = trans[w * NTAG + lane];
    if (tid < 32) fv_s[tid] = g_E[c][tid];
    __syncthreads();

    for (int lt = 0; lt < CH; lt++) {
        const bool live = maskS[lt] > 0.f;
        float nf = 0.f; int idx = lane;
        if (live) {
            float cand = (lane < NTAG) ? transS[w][lane] + fv_s[lane] : NEGINF;
#pragma unroll
            for (int s = 16; s >= 1; s >>= 1) {
                float ov = __shfl_xor_sync(0xFFFFFFFFu, cand, s);
                int   oi = __shfl_xor_sync(0xFFFFFFFFu, idx, s);
                if (ov > cand || (ov == cand && oi < idx)) { cand = ov; idx = oi; }
            }
            nf = cand + featS[lt][w];
        }
        __syncthreads();
        if (live) {
            if (lane == 0) { fv_s[w] = nf; bp_s[lt][w] = (unsigned char)idx; }
        } else {
            if (w == 0 && lane < NTAG) bp_s[lt][lane] = (unsigned char)lane;
        }
        __syncthreads();
    }

    if (c == NC - 1 && w == 0) {
        float v = (lane < NTAG) ? fv_s[lane] : NEGINF;
        int ix = lane;
#pragma unroll
        for (int s = 16; s >= 1; s >>= 1) {
            float ov = __shfl_xor_sync(0xFFFFFFFFu, v, s);
            int   oi = __shfl_xor_sync(0xFFFFFFFFu, ix, s);
            if (ov > v || (ov == v && oi < ix)) { v = ov; ix = oi; }
        }
        if (lane == 0) { g_score[0] = v; g_final[0] = ix; }
    }
    __syncthreads();

    if (tid < NTAG) {
        const int e = tid;
        int tag = e;
        g_pathLUT[(c * NTAG + e) * CH + (CH - 1)] = (unsigned char)tag;
        for (int lt = CH - 1; lt >= 1; lt--) {
            tag = bp_s[lt][tag];
            g_pathLUT[(c * NTAG + e) * CH + (lt - 1)] = (unsigned char)tag;
        }
        g_prevexit[c * NTAG + e] = bp_s[0][tag];
    }
}

// ---------------------------------------------------------------------------
// Viterbi Phase D: stitch chunks (NC-deep SMEM pointer chase) and emit output.
// ---------------------------------------------------------------------------
__global__ void __launch_bounds__(256, 1) vitD_kernel(float* __restrict__ out, int out_size)
{
    extern __shared__ unsigned char dsm[];
    unsigned char* lut = dsm;                          // NC*NTAG*CH
    unsigned char* pex = dsm + NC * NTAG * CH;         // NC*NTAG
    __shared__ int exit_s[NC];

    const int tid = threadIdx.x;
    for (int i = tid; i < NC * NTAG * CH / 16; i += 256)
        ((float4*)lut)[i] = ((const float4*)g_pathLUT)[i];
    for (int i = tid; i < NC * NTAG / 4; i += 256)
        ((int*)pex)[i] = ((const int*)g_prevexit)[i];
    __syncthreads();

    if (tid == 0) {
        int e = g_final[0];
        for (int c = NC - 1; c >= 0; c--) {
            exit_s[c] = e;
            e = pex[c * NTAG + e];
        }
        if (out_size >= 1) out[0] = g_score[0];
    }
    __syncthreads();

    if (out_size >= T_LEN + 1) {
        for (int i = tid; i < T_LEN; i += 256) {
            int c = i / CH, lt = i % CH;
            out[1 + i] = (float)lut[(c * NTAG + exit_s[c]) * CH + lt];
        }
        for (int i = T_LEN + 1 + tid; i < out_size; i += 256) out[i] = 0.f;
    } else {
        for (int i = 1 + tid; i < out_size; i += 256) out[i] = 0.f;
    }
}

// ---------------------------------------------------------------------------
extern "C" void kernel_launch(void* const* d_in, const int* in_sizes, int n_in,
                              void* d_out, int out_size)
{
    const float* sentence = (const float*)d_in[0];
    const float* mask     = (const float*)d_in[1];
    const float* w_ih_f   = (const float*)d_in[2];
    const float* w_hh_f   = (const float*)d_in[3];
    const float* b_ih_f   = (const float*)d_in[4];
    const float* b_hh_f   = (const float*)d_in[5];
    const float* w_ih_b   = (const float*)d_in[6];
    const float* w_hh_b   = (const float*)d_in[7];
    const float* b_ih_b   = (const float*)d_in[8];
    const float* b_hh_b   = (const float*)d_in[9];
    const float* w_out    = (const float*)d_in[10];
    const float* b_out    = (const float*)d_in[11];
    const float* trans    = (const float*)d_in[12];
    const int*   seq_p    = (const int*)d_in[14];

    const int B = in_sizes[0] / (T_LEN * D_IN);

    dim3 g1(T_LEN / TCHUNK, 2);
    gi_kernel<<<g1, 320>>>(sentence, w_ih_f, b_ih_f, b_hh_f,
                           w_ih_b, b_ih_b, b_hh_b, seq_p, B);
    gru_kernel<<<2, 600>>>(w_hh_f, b_hh_f, w_hh_b, b_hh_b);
    feats_kernel<<<T_LEN, 256>>>(w_out, b_out);

    vitA_kernel<<<NC, 992>>>(trans, mask, seq_p);
    vitB_kernel<<<1, 32>>>();
    vitC_kernel<<<NC, 992>>>(trans, mask, seq_p);

    const int dsm_bytes = NC * NTAG * CH + NC * NTAG;
    cudaFuncSetAttribute(vitD_kernel,
                         cudaFuncAttributeMaxDynamicSharedMemorySize, dsm_bytes);
    vitD_kernel<<<1, 256, dsm_bytes>>>((float*)d_out, out_size);
}

// round 13
// speedup vs baseline: 1.1752x; 1.1752x over previous
#include <cuda_runtime.h>
#include <cstdint>
#include <math.h>

#define T_LEN 2048
#define D_IN  100
#define HIDN  100
#define G3    300
#define GI_STRIDE 400     // interleaved gi layout: [t][unit][4] = {r,z,n,pad}
#define NTAG  31
#define NC    128         // number of viterbi chunks
#define CH    16          // steps per chunk (NC*CH == T_LEN)
#define NEGINF -1e30f

// Scratch (no allocations allowed -> __device__ globals)
__device__ float g_gi[2][T_LEN * GI_STRIDE]; // input preactivations, interleaved
__device__ float g_H[2][T_LEN * HIDN];    // hidden states (original time index)
__device__ float g_feats[T_LEN * NTAG];   // emission features for batch `seq`
__device__ float g_M[NC * NTAG * 32];     // chunk max-plus matrices, padded stride 32
__device__ float g_E[NC][32];             // chunk entry fv vectors
__device__ __align__(16) unsigned char g_pathLUT[NC * NTAG * CH]; // per-chunk path LUT
__device__ __align__(16) unsigned char g_prevexit[NC * NTAG];     // chunk exit chaining
__device__ float g_score[1];
__device__ int   g_final[1];

__device__ __forceinline__ float tanh_fast(float x) {
    float y;
    asm("tanh.approx.f32 %0, %1;" : "=f"(y) : "f"(x));
    return y;
}
// sigmoid(x) = 0.5*tanh(0.5x) + 0.5  (one MUFU instead of ex2+rcp)
__device__ __forceinline__ float sigmoid_fast(float x) {
    return fmaf(0.5f, tanh_fast(0.5f * x), 0.5f);
}

// ---------------------------------------------------------------------------
// Kernel 1: gi[t][g%100][g/100] = x[t,seq,:] . w_ih[g,:] + b_ih[g]
//           (+ b_hh[g] folded for the r,z gates)
// ---------------------------------------------------------------------------
#define TCHUNK 8
__global__ void gi_kernel(const float* __restrict__ x,
                          const float* __restrict__ w_ih_f, const float* __restrict__ b_ih_f,
                          const float* __restrict__ b_hh_f,
                          const float* __restrict__ w_ih_b, const float* __restrict__ b_ih_b,
                          const float* __restrict__ b_hh_b,
                          const int* __restrict__ seq_p, int B)
{
    const int dir = blockIdx.y;
    const float* w   = dir ? w_ih_b : w_ih_f;
    const float* b   = dir ? b_ih_b : b_ih_f;
    const float* bhh = dir ? b_hh_b : b_hh_f;
    float* out = g_gi[dir];
    const int t0 = blockIdx.x * TCHUNK;
    const int seq = *seq_p;

    __shared__ __align__(16) float xs[TCHUNK * D_IN];
    for (int idx = threadIdx.x; idx < TCHUNK * D_IN; idx += blockDim.x) {
        int tt = idx / D_IN, d = idx - tt * D_IN;
        xs[tt * D_IN + d] = x[(size_t)(t0 + tt) * B * D_IN + (size_t)seq * D_IN + d];
    }
    __syncthreads();

    const int g = threadIdx.x;
    if (g >= G3) return;

    float acc[TCHUNK];
#pragma unroll
    for (int tt = 0; tt < TCHUNK; tt++) acc[tt] = 0.f;

    const float4* wr = (const float4*)(w + g * D_IN);
#pragma unroll
    for (int i = 0; i < D_IN / 4; i++) {
        float4 w4 = wr[i];
#pragma unroll
        for (int tt = 0; tt < TCHUNK; tt++) {
            const float* xp = xs + tt * D_IN + i * 4;
            acc[tt] = fmaf(w4.x, xp[0], acc[tt]);
            acc[tt] = fmaf(w4.y, xp[1], acc[tt]);
            acc[tt] = fmaf(w4.z, xp[2], acc[tt]);
            acc[tt] = fmaf(w4.w, xp[3], acc[tt]);
        }
    }
    // fold b_hh for the r,z gates only (n gate's b_hh is multiplied by r in the cell)
    const float bb = b[g] + ((g < 2 * HIDN) ? bhh[g] : 0.f);
    const int slot = (g % HIDN) * 4 + (g / HIDN);   // interleaved {r,z,n,pad}
#pragma unroll
    for (int tt = 0; tt < TCHUNK; tt++)
        out[(size_t)(t0 + tt) * GI_STRIDE + slot] = acc[tt] + bb;
}

// ---------------------------------------------------------------------------
// Kernel 2: GRU recurrence, one CTA per direction (R8, verbatim — the proven
// fastest structure). 600 threads, thread (j=tid>>1, p=tid&1) computes half
// of gate-row j's dot with h: 13 x LDS.128 + 52 scalar FFMA. Gate threads
// (tid<100) read one LDG.128 of interleaved gi, prefetched one step ahead.
// ---------------------------------------------------------------------------
__global__ void __launch_bounds__(600, 1) gru_kernel(
    const float* __restrict__ w_hh_f, const float* __restrict__ b_hh_f,
    const float* __restrict__ w_hh_b, const float* __restrict__ b_hh_b)
{
    const int dir = blockIdx.x;
    const float* w_hh = dir ? w_hh_b : w_hh_f;
    const float* b_hh = dir ? b_hh_b : b_hh_f;
    const float* gi   = g_gi[dir];
    float* Hout       = g_H[dir];

    const int tid = threadIdx.x;
    const int j = tid >> 1;
    const int p = tid & 1;

    __shared__ __align__(16) float h_s[104];        // padded; [100..103] stay 0
    __shared__ __align__(8)  float gh_s[600];       // partials: row r at [2r],[2r+1]

    // Register-resident weights: columns [52p, 52p+52) of row j (zero pad >=100)
    float wreg[52];
#pragma unroll
    for (int i = 0; i < 52; i++) {
        int col = 52 * p + i;
        wreg[i] = (col < HIDN) ? w_hh[j * HIDN + col] : 0.f;
    }
    float bhh2 = 0.f, h_reg = 0.f;
    if (tid < HIDN) bhh2 = b_hh[2 * HIDN + tid];    // n-gate hidden bias (scaled by r)
    if (tid < 104) h_s[tid] = 0.f;
    __syncthreads();

    // gi prefetch double buffer (gate threads only)
    float4 giv = make_float4(0.f, 0.f, 0.f, 0.f);
    if (tid < HIDN) {
        const int t0 = dir ? (T_LEN - 1) : 0;
        giv = ((const float4*)(gi + (size_t)t0 * GI_STRIDE))[tid];
    }

    for (int step = 0; step < T_LEN; ++step) {
        const int t = dir ? (T_LEN - 1 - step) : step;

        // Prefetch NEXT step's gi (a full step of slack before consumption)
        float4 ginext = make_float4(0.f, 0.f, 0.f, 0.f);
        if (tid < HIDN && step + 1 < T_LEN) {
            const int tn = dir ? (T_LEN - 2 - step) : (step + 1);
            ginext = ((const float4*)(gi + (size_t)tn * GI_STRIDE))[tid];
        }

        // Matvec half-row: 13 x (LDS.128 broadcast + 4 FFMA)
        float a0 = 0.f, a1 = 0.f, a2 = 0.f, a3 = 0.f;
        const float4* hv = (const float4*)(h_s + 52 * p);
#pragma unroll
        for (int i = 0; i < 13; i++) {
            float4 h4 = hv[i];
            a0 = fmaf(wreg[4 * i + 0], h4.x, a0);
            a1 = fmaf(wreg[4 * i + 1], h4.y, a1);
            a2 = fmaf(wreg[4 * i + 2], h4.z, a2);
            a3 = fmaf(wreg[4 * i + 3], h4.w, a3);
        }
        gh_s[2 * j + p] = (a0 + a1) + (a2 + a3);
        __syncthreads();

        if (tid < HIDN) {
            const float2* g2 = (const float2*)gh_s;
            float2 pr = g2[tid];                // row tid       (r gate)
            float2 pz = g2[HIDN + tid];         // row 100+tid   (z gate)
            float2 pn = g2[2 * HIDN + tid];     // row 200+tid   (n gate)
            float r = sigmoid_fast(giv.x + pr.x + pr.y);
            float z = sigmoid_fast(giv.y + pz.x + pz.y);
            float hn = (pn.x + pn.y) + bhh2;
            float n = tanh_fast(fmaf(r, hn, giv.z));
            float hnew = fmaf(z, h_reg - n, n);
            h_reg = hnew;
            Hout[(size_t)t * HIDN + tid] = hnew;
            h_s[tid] = hnew;    // safe: all matvec reads finished before sync above
        }
        giv = ginext;
        __syncthreads();
    }
}

// ---------------------------------------------------------------------------
// Kernel 3: feats[t][k] = w_out[k,:] . [h_f[t]; h_b[t]] + b_out[k]
// ---------------------------------------------------------------------------
__global__ void feats_kernel(const float* __restrict__ w_out, const float* __restrict__ b_out)
{
    const int t = blockIdx.x;
    __shared__ __align__(16) float hc[2 * HIDN];
    const int tid = threadIdx.x;
    if (tid < HIDN)          hc[tid] = g_H[0][(size_t)t * HIDN + tid];
    else if (tid < 2 * HIDN) hc[tid] = g_H[1][(size_t)t * HIDN + (tid - HIDN)];
    __syncthreads();

    if (tid < NTAG) {
        const float4* wr = (const float4*)(w_out + tid * 2 * HIDN);
        const float4* hv = (const float4*)hc;
        float a0 = 0.f, a1 = 0.f, a2 = 0.f, a3 = 0.f;
#pragma unroll
        for (int i = 0; i < (2 * HIDN) / 4; i++) {
            float4 w4 = wr[i]; float4 h4 = hv[i];
            a0 = fmaf(w4.x, h4.x, a0); a1 = fmaf(w4.y, h4.y, a1);
            a2 = fmaf(w4.z, h4.z, a2); a3 = fmaf(w4.w, h4.w, a3);
        }
        g_feats[t * NTAG + tid] = (a0 + a1) + (a2 + a3) + b_out[tid];
    }
}

// ---------------------------------------------------------------------------
// Viterbi Phase A: per-chunk max-plus matrix product, NC CTAs in parallel.
// ---------------------------------------------------------------------------
__global__ void __launch_bounds__(992, 1) vitA_kernel(
    const float* __restrict__ trans, const float* __restrict__ maskg,
    const int* __restrict__ seq_p)
{
    const int c = blockIdx.x;
    const int tid = threadIdx.x;
    const int w = tid >> 5;
    const int lane = tid & 31;
    const int seq = *seq_p;

    __shared__ float Mbuf[2][NTAG][32];
    __shared__ float featS[CH][32];
    __shared__ float maskS[CH];

    if (tid < CH * NTAG) {
        int lt = tid / NTAG, k = tid - lt * NTAG;
        featS[lt][k] = g_feats[(c * CH + lt) * NTAG + k];
    }
    if (tid < CH) maskS[tid] = maskg[(size_t)seq * T_LEN + c * CH + tid];

    for (int idx = tid; idx < 2 * NTAG * 32; idx += 992) {
        int buf = idx / (NTAG * 32);
        int rem = idx - buf * NTAG * 32;
        int r = rem >> 5, col = rem & 31;
        Mbuf[buf][r][col] = (r == col) ? 0.f : NEGINF;
    }

    float tr[NTAG];
#pragma unroll
    for (int jj = 0; jj < NTAG; jj++) tr[jj] = trans[w * NTAG + jj];
    __syncthreads();

    int src = 0;
    for (int lt = 0; lt < CH; lt++) {
        if (maskS[lt] > 0.f) {
            float f = featS[lt][w];
            float m = NEGINF;
#pragma unroll
            for (int jj = 0; jj < NTAG; jj++)
                m = fmaxf(m, tr[jj] + Mbuf[src][jj][lane]);
            Mbuf[1 - src][w][lane] = m + f;
            __syncthreads();
            src ^= 1;
        }
    }
    g_M[c * NTAG * 32 + w * 32 + lane] = Mbuf[src][w][lane];
}

// ---------------------------------------------------------------------------
// Viterbi Phase B: sequential chunk combine (single warp) with prefetch.
// ---------------------------------------------------------------------------
__global__ void __launch_bounds__(32, 1) vitB_kernel()
{
    const int lane = threadIdx.x;
    const int rowi = (lane < NTAG) ? lane : NTAG - 1;
    float fv = (lane == 0) ? 0.f : ((lane < NTAG) ? -10000.f : NEGINF);

    float cur[32], pre[32];
    {
        const float4* r4 = (const float4*)(g_M + 0 * NTAG * 32 + rowi * 32);
#pragma unroll
        for (int i = 0; i < 8; i++) {
            float4 v = r4[i];
            cur[4 * i] = v.x; cur[4 * i + 1] = v.y; cur[4 * i + 2] = v.z; cur[4 * i + 3] = v.w;
        }
    }

    for (int c = 0; c < NC; c++) {
        if (c + 1 < NC) {
            const float4* r4 = (const float4*)(g_M + (c + 1) * NTAG * 32 + rowi * 32);
#pragma unroll
            for (int i = 0; i < 8; i++) {
                float4 v = r4[i];
                pre[4 * i] = v.x; pre[4 * i + 1] = v.y; pre[4 * i + 2] = v.z; pre[4 * i + 3] = v.w;
            }
        }
        g_E[c][lane] = fv;
        float m = NEGINF;
#pragma unroll
        for (int pp = 0; pp < NTAG; pp++)
            m = fmaxf(m, cur[pp] + __shfl_sync(0xFFFFFFFFu, fv, pp));
        fv = (lane < NTAG) ? m : NEGINF;
#pragma unroll
        for (int i = 0; i < 32; i++) cur[i] = pre[i];
    }
}

// ---------------------------------------------------------------------------
// Viterbi Phase C: per-chunk forward re-run + backpointers + backtrack LUT.
// ---------------------------------------------------------------------------
__global__ void __launch_bounds__(992, 1) vitC_kernel(
    const float* __restrict__ trans, const float* __restrict__ maskg,
    const int* __restrict__ seq_p)
{
    const int c = blockIdx.x;
    const int tid = threadIdx.x;
    const int w = tid >> 5;
    const int lane = tid & 31;
    const int seq = *seq_p;

    __shared__ float fv_s[32];
    __shared__ float transS[NTAG][32];
    __shared__ float featS[CH][32];
    __shared__ float maskS[CH];
    __shared__ unsigned char bp_s[CH][NTAG];

    if (tid < CH * NTAG) {
        int lt = tid / NTAG, k = tid - lt * NTAG;
        featS[lt][k] = g_feats[(c * CH + lt) * NTAG + k];
    }
    if (tid < CH) maskS[tid] = maskg[(size_t)seq * T_LEN + c * CH + tid];
    if (lane < NTAG) transS[w][lane] = trans[w * NTAG + lane];
    if (tid < 32) fv_s[tid] = g_E[c][tid];
    __syncthreads();

    for (int lt = 0; lt < CH; lt++) {
        const bool live = maskS[lt] > 0.f;
        float nf = 0.f; int idx = lane;
        if (live) {
            float cand = (lane < NTAG) ? transS[w][lane] + fv_s[lane] : NEGINF;
#pragma unroll
            for (int s = 16; s >= 1; s >>= 1) {
                float ov = __shfl_xor_sync(0xFFFFFFFFu, cand, s);
                int   oi = __shfl_xor_sync(0xFFFFFFFFu, idx, s);
                if (ov > cand || (ov == cand && oi < idx)) { cand = ov; idx = oi; }
            }
            nf = cand + featS[lt][w];
        }
        __syncthreads();
        if (live) {
            if (lane == 0) { fv_s[w] = nf; bp_s[lt][w] = (unsigned char)idx; }
        } else {
            if (w == 0 && lane < NTAG) bp_s[lt][lane] = (unsigned char)lane;
        }
        __syncthreads();
    }

    if (c == NC - 1 && w == 0) {
        float v = (lane < NTAG) ? fv_s[lane] : NEGINF;
        int ix = lane;
#pragma unroll
        for (int s = 16; s >= 1; s >>= 1) {
            float ov = __shfl_xor_sync(0xFFFFFFFFu, v, s);
            int   oi = __shfl_xor_sync(0xFFFFFFFFu, ix, s);
            if (ov > v || (ov == v && oi < ix)) { v = ov; ix = oi; }
        }
        if (lane == 0) { g_score[0] = v; g_final[0] = ix; }
    }
    __syncthreads();

    if (tid < NTAG) {
        const int e = tid;
        int tag = e;
        g_pathLUT[(c * NTAG + e) * CH + (CH - 1)] = (unsigned char)tag;
        for (int lt = CH - 1; lt >= 1; lt--) {
            tag = bp_s[lt][tag];
            g_pathLUT[(c * NTAG + e) * CH + (lt - 1)] = (unsigned char)tag;
        }
        g_prevexit[c * NTAG + e] = bp_s[0][tag];
    }
}

// ---------------------------------------------------------------------------
// Viterbi Phase D: stitch chunks (NC-deep SMEM pointer chase) and emit output.
// ---------------------------------------------------------------------------
__global__ void __launch_bounds__(256, 1) vitD_kernel(float* __restrict__ out, int out_size)
{
    extern __shared__ unsigned char dsm[];
    unsigned char* lut = dsm;                          // NC*NTAG*CH
    unsigned char* pex = dsm + NC * NTAG * CH;         // NC*NTAG
    __shared__ int exit_s[NC];

    const int tid = threadIdx.x;
    for (int i = tid; i < NC * NTAG * CH / 16; i += 256)
        ((float4*)lut)[i] = ((const float4*)g_pathLUT)[i];
    for (int i = tid; i < NC * NTAG / 4; i += 256)
        ((int*)pex)[i] = ((const int*)g_prevexit)[i];
    __syncthreads();

    if (tid == 0) {
        int e = g_final[0];
        for (int c = NC - 1; c >= 0; c--) {
            exit_s[c] = e;
            e = pex[c * NTAG + e];
        }
        if (out_size >= 1) out[0] = g_score[0];
    }
    __syncthreads();

    if (out_size >= T_LEN + 1) {
        for (int i = tid; i < T_LEN; i += 256) {
            int c = i / CH, lt = i % CH;
            out[1 + i] = (float)lut[(c * NTAG + exit_s[c]) * CH + lt];
        }
        for (int i = T_LEN + 1 + tid; i < out_size; i += 256) out[i] = 0.f;
    } else {
        for (int i = 1 + tid; i < out_size; i += 256) out[i] = 0.f;
    }
}

// ---------------------------------------------------------------------------
extern "C" void kernel_launch(void* const* d_in, const int* in_sizes, int n_in,
                              void* d_out, int out_size)
{
    const float* sentence = (const float*)d_in[0];
    const float* mask     = (const float*)d_in[1];
    const float* w_ih_f   = (const float*)d_in[2];
    const float* w_hh_f   = (const float*)d_in[3];
    const float* b_ih_f   = (const float*)d_in[4];
    const float* b_hh_f   = (const float*)d_in[5];
    const float* w_ih_b   = (const float*)d_in[6];
    const float* w_hh_b   = (const float*)d_in[7];
    const float* b_ih_b   = (const float*)d_in[8];
    const float* b_hh_b   = (const float*)d_in[9];
    const float* w_out    = (const float*)d_in[10];
    const float* b_out    = (const float*)d_in[11];
    const float* trans    = (const float*)d_in[12];
    const int*   seq_p    = (const int*)d_in[14];

    const int B = in_sizes[0] / (T_LEN * D_IN);

    dim3 g1(T_LEN / TCHUNK, 2);
    gi_kernel<<<g1, 320>>>(sentence, w_ih_f, b_ih_f, b_hh_f,
                           w_ih_b, b_ih_b, b_hh_b, seq_p, B);
    gru_kernel<<<2, 600>>>(w_hh_f, b_hh_f, w_hh_b, b_hh_b);
    feats_kernel<<<T_LEN, 256>>>(w_out, b_out);

    vitA_kernel<<<NC, 992>>>(trans, mask, seq_p);
    vitB_kernel<<<1, 32>>>();
    vitC_kernel<<<NC, 992>>>(trans, mask, seq_p);

    const int dsm_bytes = NC * NTAG * CH + NC * NTAG;
    cudaFuncSetAttribute(vitD_kernel,
                         cudaFuncAttributeMaxDynamicSharedMemorySize, dsm_bytes);
    vitD_kernel<<<1, 256, dsm_bytes>>>((float*)d_out, out_size);
}